// round 1
// baseline (speedup 1.0000x reference)
#include <cuda_runtime.h>

#define NN    4096
#define FIN   512
#define FHID  256
#define FCLS  16
#define NHD   4
#define NEGINF (-9000000000000000.0f)

// ---------------- scratch (static device globals; no allocs allowed) --------
__device__ float g_h1  [NHD*NN*FHID];   // 16 MB  layer1 per-head features
__device__ float g_out1[NHD*NN*FHID];   // 16 MB  layer1 per-head attention output
__device__ float g_esrc1[NHD*NN];
__device__ float g_edst1[NHD*NN];
__device__ float g_max1 [NHD*NN];
__device__ float g_Z1   [NHD*NN];
__device__ float g_hmid[NN*FHID];       // 4 MB   relu(mean over heads)
__device__ float g_h2  [NN*FCLS];
__device__ float g_esrc2[NN];
__device__ float g_edst2[NN];
__device__ float g_max2 [NN];
__device__ float g_Z2   [NN];

__device__ __forceinline__ float lrelu(float v) { return v >= 0.0f ? v : 0.2f * v; }

// ---------------- K1: h1[h] = x @ W1[h]  (M=4096, K=512, N=256) -------------
// BM=64, BN=128, BK=16, 256 threads, 4x8 micro-tile.
__global__ __launch_bounds__(256) void k1_gemm(const float* __restrict__ X,
                                               const float* __restrict__ W1) {
    __shared__ float As[64][16];
    __shared__ float Bs[16][128];
    const int h  = blockIdx.z;
    const int n0 = blockIdx.x * 64;
    const int o0 = blockIdx.y * 128;
    const float* B = W1 + h * FIN * FHID;
    const int tid = threadIdx.x;
    const int tr = tid >> 4, tc = tid & 15;
    const int kk = tid & 15, nl = tid >> 4;
    const int oo = tid & 127, k2 = tid >> 7;

    float acc[4][8];
#pragma unroll
    for (int i = 0; i < 4; i++)
#pragma unroll
        for (int j = 0; j < 8; j++) acc[i][j] = 0.0f;

    for (int k0 = 0; k0 < FIN; k0 += 16) {
#pragma unroll
        for (int r = 0; r < 4; r++)
            As[nl + 16*r][kk] = X[(n0 + nl + 16*r) * FIN + k0 + kk];
#pragma unroll
        for (int r = 0; r < 8; r++)
            Bs[k2 + 2*r][oo] = B[(k0 + k2 + 2*r) * FHID + o0 + oo];
        __syncthreads();
#pragma unroll
        for (int k = 0; k < 16; k++) {
            float a[4];
#pragma unroll
            for (int i = 0; i < 4; i++) a[i] = As[tr*4 + i][k];
            float4 b0 = *(const float4*)&Bs[k][tc*8];
            float4 b1 = *(const float4*)&Bs[k][tc*8 + 4];
#pragma unroll
            for (int i = 0; i < 4; i++) {
                acc[i][0] += a[i]*b0.x; acc[i][1] += a[i]*b0.y;
                acc[i][2] += a[i]*b0.z; acc[i][3] += a[i]*b0.w;
                acc[i][4] += a[i]*b1.x; acc[i][5] += a[i]*b1.y;
                acc[i][6] += a[i]*b1.z; acc[i][7] += a[i]*b1.w;
            }
        }
        __syncthreads();
    }
    float* out = g_h1 + (size_t)h * NN * FHID;
#pragma unroll
    for (int i = 0; i < 4; i++)
#pragma unroll
        for (int j = 0; j < 8; j++)
            out[(n0 + tr*4 + i) * FHID + o0 + tc*8 + j] = acc[i][j];
}

// ---------------- K1e: e_src/e_dst dot products (one warp per (h,n)) --------
__global__ __launch_bounds__(256) void k_edot(const float* __restrict__ a1) {
    const int w    = (blockIdx.x * blockDim.x + threadIdx.x) >> 5;  // 0..16383
    const int lane = threadIdx.x & 31;
    const int h = w >> 12;        // /4096
    const int n = w & (NN - 1);
    const float* hrow = g_h1 + ((size_t)h * NN + n) * FHID;
    const float* asrc = a1 + h * 2 * FHID;
    const float* adst = asrc + FHID;
    float s = 0.0f, d = 0.0f;
#pragma unroll
    for (int o = lane; o < FHID; o += 32) {
        float v = hrow[o];
        s += v * asrc[o];
        d += v * adst[o];
    }
#pragma unroll
    for (int off = 16; off; off >>= 1) {
        s += __shfl_xor_sync(0xffffffffu, s, off);
        d += __shfl_xor_sync(0xffffffffu, d, off);
    }
    if (lane == 0) { g_esrc1[h*NN + n] = s; g_edst1[h*NN + n] = d; }
}

// ---------------- K2: per-row softmax stats, layer 1 (4 heads, block/row) ---
__global__ __launch_bounds__(256) void k2_stats1(const int* __restrict__ adj) {
    __shared__ unsigned char sadj[NN];
    __shared__ float red[8][NHD];
    const int n = blockIdx.x, tid = threadIdx.x;
    const int lane = tid & 31, wid = tid >> 5;
    const int* arow = adj + (size_t)n * NN;
    for (int m = tid; m < NN; m += 256) sadj[m] = (unsigned char)(arow[m] != 0);
    __syncthreads();

    float s[NHD], mx[NHD];
#pragma unroll
    for (int h = 0; h < NHD; h++) { s[h] = g_esrc1[h*NN + n]; mx[h] = NEGINF; }

    for (int m = tid; m < NN; m += 256) {
        bool a = sadj[m] != 0;
#pragma unroll
        for (int h = 0; h < NHD; h++) {
            float v = a ? lrelu(s[h] + g_edst1[h*NN + m]) : NEGINF;
            mx[h] = fmaxf(mx[h], v);
        }
    }
#pragma unroll
    for (int h = 0; h < NHD; h++)
#pragma unroll
        for (int off = 16; off; off >>= 1)
            mx[h] = fmaxf(mx[h], __shfl_xor_sync(0xffffffffu, mx[h], off));
    if (lane == 0)
#pragma unroll
        for (int h = 0; h < NHD; h++) red[wid][h] = mx[h];
    __syncthreads();

    float rm[NHD];
#pragma unroll
    for (int h = 0; h < NHD; h++) {
        float t = red[0][h];
#pragma unroll
        for (int w = 1; w < 8; w++) t = fmaxf(t, red[w][h]);
        rm[h] = t;
    }
    __syncthreads();

    float sum[NHD];
#pragma unroll
    for (int h = 0; h < NHD; h++) sum[h] = 0.0f;
    for (int m = tid; m < NN; m += 256) {
        bool a = sadj[m] != 0;
#pragma unroll
        for (int h = 0; h < NHD; h++) {
            float v = a ? lrelu(s[h] + g_edst1[h*NN + m]) : NEGINF;
            sum[h] += __expf(v - rm[h]);
        }
    }
#pragma unroll
    for (int h = 0; h < NHD; h++)
#pragma unroll
        for (int off = 16; off; off >>= 1)
            sum[h] += __shfl_xor_sync(0xffffffffu, sum[h], off);
    if (lane == 0)
#pragma unroll
        for (int h = 0; h < NHD; h++) red[wid][h] = sum[h];
    __syncthreads();
    if (tid == 0) {
#pragma unroll
        for (int h = 0; h < NHD; h++) {
            float t = 0.0f;
#pragma unroll
            for (int w = 0; w < 8; w++) t += red[w][h];
            g_max1[h*NN + n] = rm[h];
            g_Z1  [h*NN + n] = t;
        }
    }
}

// ---------------- K3: out1[h] = softmax(e) @ h1[h] --------------------------
// Tiled GEMM, A-tile (attention probs) generated on the fly in smem.
// BM=64, BN=128, BK=16, 256 threads, 4x8 micro-tile. K-loop = 4096/16 = 256.
__global__ __launch_bounds__(256) void k3_attn(const int* __restrict__ adj) {
    __shared__ float As[64][16];
    __shared__ float Bs[16][128];
    __shared__ float s_es[64], s_mx[64], s_Z[64];
    const int h  = blockIdx.z;
    const int n0 = blockIdx.x * 64;
    const int o0 = blockIdx.y * 128;
    const int tid = threadIdx.x;
    if (tid < 64) {
        s_es[tid] = g_esrc1[h*NN + n0 + tid];
        s_mx[tid] = g_max1 [h*NN + n0 + tid];
        s_Z [tid] = g_Z1   [h*NN + n0 + tid];
    }
    __syncthreads();
    const int tr = tid >> 4, tc = tid & 15;
    const int kk = tid & 15, nl = tid >> 4;
    const int oo = tid & 127, k2 = tid >> 7;
    const float* Bsrc = g_h1 + (size_t)h * NN * FHID;
    const float* edst = g_edst1 + h * NN;

    float acc[4][8];
#pragma unroll
    for (int i = 0; i < 4; i++)
#pragma unroll
        for (int j = 0; j < 8; j++) acc[i][j] = 0.0f;

    for (int m0 = 0; m0 < NN; m0 += 16) {
        float d = edst[m0 + kk];
#pragma unroll
        for (int r = 0; r < 4; r++) {
            int row = nl + 16*r;
            int a = adj[(n0 + row) * NN + m0 + kk];
            float v = a ? lrelu(s_es[row] + d) : NEGINF;
            As[row][kk] = __expf(v - s_mx[row]);
        }
#pragma unroll
        for (int r = 0; r < 8; r++)
            Bs[k2 + 2*r][oo] = Bsrc[(m0 + k2 + 2*r) * FHID + o0 + oo];
        __syncthreads();
#pragma unroll
        for (int k = 0; k < 16; k++) {
            float a[4];
#pragma unroll
            for (int i = 0; i < 4; i++) a[i] = As[tr*4 + i][k];
            float4 b0 = *(const float4*)&Bs[k][tc*8];
            float4 b1 = *(const float4*)&Bs[k][tc*8 + 4];
#pragma unroll
            for (int i = 0; i < 4; i++) {
                acc[i][0] += a[i]*b0.x; acc[i][1] += a[i]*b0.y;
                acc[i][2] += a[i]*b0.z; acc[i][3] += a[i]*b0.w;
                acc[i][4] += a[i]*b1.x; acc[i][5] += a[i]*b1.y;
                acc[i][6] += a[i]*b1.z; acc[i][7] += a[i]*b1.w;
            }
        }
        __syncthreads();
    }
    float* out = g_out1 + (size_t)h * NN * FHID;
#pragma unroll
    for (int i = 0; i < 4; i++) {
        float invZ = 1.0f / s_Z[tr*4 + i];
#pragma unroll
        for (int j = 0; j < 8; j++)
            out[(n0 + tr*4 + i) * FHID + o0 + tc*8 + j] = acc[i][j] * invZ;
    }
}

// ---------------- K4: hmid = relu(mean over heads of out1) ------------------
__global__ __launch_bounds__(256) void k4_meanrelu() {
    const int i = blockIdx.x * 256 + threadIdx.x;   // NN*FHID threads
    const int S = NN * FHID;
    float v = 0.25f * (g_out1[i] + g_out1[i + S] + g_out1[i + 2*S] + g_out1[i + 3*S]);
    g_hmid[i] = v > 0.0f ? v : 0.0f;
}

// ---------------- K5: h2 = hmid @ W2[0]  + e2 dot products ------------------
// 256 threads = 16 rows x 16 classes per block.
__global__ __launch_bounds__(256) void k5_layer2(const float* __restrict__ W2,
                                                 const float* __restrict__ a2) {
    __shared__ float sW[FHID * FCLS];
    const int tid = threadIdx.x;
    for (int i = tid; i < FHID * FCLS; i += 256) sW[i] = W2[i];
    __syncthreads();
    const int r = tid >> 4;          // 0..15 row within block
    const int o = tid & 15;          // class
    const int n = blockIdx.x * 16 + r;
    const float* hr = g_hmid + (size_t)n * FHID;
    float v = 0.0f;
#pragma unroll 8
    for (int f = 0; f < FHID; f++) v += hr[f] * sW[f * FCLS + o];
    g_h2[n * FCLS + o] = v;
    float vs = v * a2[o];
    float vd = v * a2[FCLS + o];
#pragma unroll
    for (int off = 8; off; off >>= 1) {
        vs += __shfl_xor_sync(0xffffffffu, vs, off);
        vd += __shfl_xor_sync(0xffffffffu, vd, off);
    }
    if (o == 0) { g_esrc2[n] = vs; g_edst2[n] = vd; }
}

// ---------------- K6: per-row softmax stats, layer 2 (1 head) ---------------
__global__ __launch_bounds__(256) void k6_stats2(const int* __restrict__ adj) {
    __shared__ unsigned char sadj[NN];
    __shared__ float red[8];
    const int n = blockIdx.x, tid = threadIdx.x;
    const int lane = tid & 31, wid = tid >> 5;
    const int* arow = adj + (size_t)n * NN;
    for (int m = tid; m < NN; m += 256) sadj[m] = (unsigned char)(arow[m] != 0);
    __syncthreads();

    const float s = g_esrc2[n];
    float mx = NEGINF;
    for (int m = tid; m < NN; m += 256) {
        float v = sadj[m] ? lrelu(s + g_edst2[m]) : NEGINF;
        mx = fmaxf(mx, v);
    }
#pragma unroll
    for (int off = 16; off; off >>= 1) mx = fmaxf(mx, __shfl_xor_sync(0xffffffffu, mx, off));
    if (lane == 0) red[wid] = mx;
    __syncthreads();
    float rm = red[0];
#pragma unroll
    for (int w = 1; w < 8; w++) rm = fmaxf(rm, red[w]);
    __syncthreads();

    float sum = 0.0f;
    for (int m = tid; m < NN; m += 256) {
        float v = sadj[m] ? lrelu(s + g_edst2[m]) : NEGINF;
        sum += __expf(v - rm);
    }
#pragma unroll
    for (int off = 16; off; off >>= 1) sum += __shfl_xor_sync(0xffffffffu, sum, off);
    if (lane == 0) red[wid] = sum;
    __syncthreads();
    if (tid == 0) {
        float t = 0.0f;
#pragma unroll
        for (int w = 0; w < 8; w++) t += red[w];
        g_max2[n] = rm;
        g_Z2[n]   = t;
    }
}

// ---------------- K7: out = log_softmax(softmax(e2) @ h2) -------------------
// 4 rows per block, 256 threads; each thread accumulates 4x16 partials over m.
__global__ __launch_bounds__(256) void k7_out(const int* __restrict__ adj,
                                              float* __restrict__ out) {
    const int n0 = blockIdx.x * 4;
    const int tid = threadIdx.x, lane = tid & 31, wid = tid >> 5;
    __shared__ float sacc[8][4 * FCLS];

    float s[4], rm[4];
#pragma unroll
    for (int r = 0; r < 4; r++) { s[r] = g_esrc2[n0 + r]; rm[r] = g_max2[n0 + r]; }

    float acc[4][16];
#pragma unroll
    for (int r = 0; r < 4; r++)
#pragma unroll
        for (int o = 0; o < 16; o++) acc[r][o] = 0.0f;

    for (int m = tid; m < NN; m += 256) {
        float d = g_edst2[m];
        float4 h0 = *(const float4*)&g_h2[m * FCLS];
        float4 h1v = *(const float4*)&g_h2[m * FCLS + 4];
        float4 h2v = *(const float4*)&g_h2[m * FCLS + 8];
        float4 h3v = *(const float4*)&g_h2[m * FCLS + 12];
#pragma unroll
        for (int r = 0; r < 4; r++) {
            int a = adj[(size_t)(n0 + r) * NN + m];
            float v = a ? lrelu(s[r] + d) : NEGINF;
            float p = __expf(v - rm[r]);
            acc[r][0]  += p * h0.x;  acc[r][1]  += p * h0.y;
            acc[r][2]  += p * h0.z;  acc[r][3]  += p * h0.w;
            acc[r][4]  += p * h1v.x; acc[r][5]  += p * h1v.y;
            acc[r][6]  += p * h1v.z; acc[r][7]  += p * h1v.w;
            acc[r][8]  += p * h2v.x; acc[r][9]  += p * h2v.y;
            acc[r][10] += p * h2v.z; acc[r][11] += p * h2v.w;
            acc[r][12] += p * h3v.x; acc[r][13] += p * h3v.y;
            acc[r][14] += p * h3v.z; acc[r][15] += p * h3v.w;
        }
    }
#pragma unroll
    for (int r = 0; r < 4; r++)
#pragma unroll
        for (int o = 0; o < 16; o++)
#pragma unroll
            for (int off = 16; off; off >>= 1)
                acc[r][o] += __shfl_xor_sync(0xffffffffu, acc[r][o], off);
    if (lane == 0)
#pragma unroll
        for (int r = 0; r < 4; r++)
#pragma unroll
            for (int o = 0; o < 16; o++) sacc[wid][r * 16 + o] = acc[r][o];
    __syncthreads();

    if (tid < 64) {
        int r = tid >> 4;
        float t = 0.0f;
#pragma unroll
        for (int w = 0; w < 8; w++) t += sacc[w][tid];
        t /= g_Z2[n0 + r];
        sacc[0][tid] = t;
    }
    __syncthreads();
    if (tid < 4) {
        float vmax = -3.4e38f;
#pragma unroll
        for (int o = 0; o < 16; o++) vmax = fmaxf(vmax, sacc[0][tid * 16 + o]);
        float se = 0.0f;
#pragma unroll
        for (int o = 0; o < 16; o++) se += __expf(sacc[0][tid * 16 + o] - vmax);
        float l = vmax + logf(se);
#pragma unroll
        for (int o = 0; o < 16; o++)
            out[(size_t)(n0 + tid) * FCLS + o] = sacc[0][tid * 16 + o] - l;
    }
}

// ---------------------------------------------------------------------------
extern "C" void kernel_launch(void* const* d_in, const int* in_sizes, int n_in,
                              void* d_out, int out_size) {
    const float* x   = (const float*)d_in[0];   // [4096,512]
    const int*   adj = (const int*)  d_in[1];   // [4096,4096]
    const float* W1  = (const float*)d_in[2];   // [4,512,256]
    const float* a1  = (const float*)d_in[3];   // [4,512]
    const float* W2  = (const float*)d_in[4];   // [1,256,16]
    const float* a2  = (const float*)d_in[5];   // [1,32]
    float* out = (float*)d_out;                 // [4096,16]

    dim3 g1(NN / 64, FHID / 128, NHD);
    k1_gemm<<<g1, 256>>>(x, W1);
    k_edot<<<(NHD * NN) / 8, 256>>>(a1);
    k2_stats1<<<NN, 256>>>(adj);
    dim3 g3(NN / 64, FHID / 128, NHD);
    k3_attn<<<g3, 256>>>(adj);
    k4_meanrelu<<<(NN * FHID) / 256, 256>>>();
    k5_layer2<<<NN / 16, 256>>>(W2, a2);
    k6_stats2<<<NN, 256>>>(adj);
    k7_out<<<NN / 4, 256>>>(adj, out);
}

// round 2
// speedup vs baseline: 5.0076x; 5.0076x over previous
#include <cuda_runtime.h>
#include <cuda_bf16.h>
#include <cstdint>

#define NN    4096
#define FIN   512
#define FHID  256
#define FCLS  16
#define NHD   4

// ---------------- scratch (static device globals) ---------------------------
__device__ __nv_bfloat16 g_P1  [(size_t)NHD*NN*NN];   // 128 MB attention probs (unnormalized)
__device__ float         g_h1f [NHD*NN*FHID];         // 16 MB
__device__ __nv_bfloat16 g_h1b [NHD*NN*FHID];         // 8 MB
__device__ float         g_out1[NHD*NN*FHID];         // 16 MB
__device__ float         g_hmid[NN*FHID];             // 4 MB
__device__ __nv_bfloat16 g_xb  [NN*FIN];              // 4 MB
__device__ __nv_bfloat16 g_W1b [NHD*FIN*FHID];        // 1 MB
__device__ unsigned      g_adjbits[(size_t)NN*NN/32]; // 2 MB
__device__ float g_esrc1[NHD*NN], g_edst1[NHD*NN], g_Z1[NHD*NN];
__device__ float g_A11[NHD*NN], g_A21[NHD*NN], g_B11[NHD*NN], g_B21[NHD*NN];
__device__ float g_h2[NN*FCLS];
__device__ float g_esrc2[NN], g_edst2[NN];
__device__ float g_A12[NN], g_A22[NN], g_B12[NN], g_B22[NN];

// ---------------- helpers ----------------------------------------------------
__device__ __forceinline__ void mma16816(float* c, const uint32_t* a, const uint32_t* b) {
    asm volatile("mma.sync.aligned.m16n8k16.row.col.f32.bf16.bf16.f32 "
                 "{%0,%1,%2,%3}, {%4,%5,%6,%7}, {%8,%9}, {%0,%1,%2,%3};\n"
                 : "+f"(c[0]), "+f"(c[1]), "+f"(c[2]), "+f"(c[3])
                 : "r"(a[0]), "r"(a[1]), "r"(a[2]), "r"(a[3]),
                   "r"(b[0]), "r"(b[1]));
}
__device__ __forceinline__ void ldsm_x4(uint32_t* r, const void* p) {
    uint32_t a = (uint32_t)__cvta_generic_to_shared(p);
    asm volatile("ldmatrix.sync.aligned.m8n8.x4.shared.b16 {%0,%1,%2,%3}, [%4];"
                 : "=r"(r[0]), "=r"(r[1]), "=r"(r[2]), "=r"(r[3]) : "r"(a));
}
__device__ __forceinline__ void ldsm_x4_t(uint32_t* r, const void* p) {
    uint32_t a = (uint32_t)__cvta_generic_to_shared(p);
    asm volatile("ldmatrix.sync.aligned.m8n8.x4.trans.shared.b16 {%0,%1,%2,%3}, [%4];"
                 : "=r"(r[0]), "=r"(r[1]), "=r"(r[2]), "=r"(r[3]) : "r"(a));
}

// ---------------- conversions ------------------------------------------------
__global__ void k_cvt(const float* __restrict__ src, __nv_bfloat16* __restrict__ dst, int n) {
    int i = blockIdx.x * 256 + threadIdx.x;
    if (i < n) dst[i] = __float2bfloat16(src[i]);
}

// ---------------- adjacency bit-pack ----------------------------------------
__global__ void k_pack(const int* __restrict__ adj) {
    int w = blockIdx.x * 8 + (threadIdx.x >> 5);
    int lane = threadIdx.x & 31;
    int v = adj[(size_t)w * 32 + lane];
    unsigned m = __ballot_sync(0xffffffffu, v != 0);
    if (lane == 0) g_adjbits[w] = m;
}

// ---------------- bf16 tensor-core GEMM (BM=128 BN=128 BK=32, 256 thr) ------
// mode 0: h1 = xb @ W1b[h]   (M=4096 N=256 K=512), writes h1f + h1b
// mode 1: out1 = P1[h] @ h1b[h] (M=4096 N=256 K=4096), writes out1 * invZ
__global__ __launch_bounds__(256) void k_gemm_mma(int mode) {
    const int h = blockIdx.z;
    const __nv_bfloat16 *A, *Bp;
    float* Cf; __nv_bfloat16* Cb; const float* Zr;
    int K;
    if (mode == 0) {
        A = g_xb; Bp = g_W1b + (size_t)h * FIN * FHID;
        Cf = g_h1f + (size_t)h * NN * FHID; Cb = g_h1b + (size_t)h * NN * FHID;
        Zr = nullptr; K = FIN;
    } else {
        A = g_P1 + (size_t)h * NN * NN; Bp = g_h1b + (size_t)h * NN * FHID;
        Cf = g_out1 + (size_t)h * NN * FHID; Cb = nullptr;
        Zr = g_Z1 + h * NN; K = NN;
    }
    const int N = FHID;
    const int bm = blockIdx.x * 128;
    const int bn = blockIdx.y * 128;

    __shared__ __nv_bfloat16 As[128 * 40];   // padded stride 40
    __shared__ __nv_bfloat16 Bs[32 * 136];   // padded stride 136

    const int tid = threadIdx.x;
    const int warp = tid >> 5, lane = tid & 31;
    const int wm = warp & 3, wn = warp >> 2;   // 4x2 warp grid, warp tile 32x64

    float acc[2][8][4];
#pragma unroll
    for (int t = 0; t < 2; t++)
#pragma unroll
        for (int j = 0; j < 8; j++)
#pragma unroll
            for (int i = 0; i < 4; i++) acc[t][j][i] = 0.0f;

    for (int k0 = 0; k0 < K; k0 += 32) {
        // load A tile 128x32 (512 uint4 chunks)
#pragma unroll
        for (int c0 = 0; c0 < 2; c0++) {
            int c = tid + c0 * 256;
            int row = c >> 2, cc = c & 3;
            *(uint4*)&As[row * 40 + cc * 8] =
                *(const uint4*)&A[(size_t)(bm + row) * K + k0 + cc * 8];
        }
        // load B tile 32x128
#pragma unroll
        for (int c0 = 0; c0 < 2; c0++) {
            int c = tid + c0 * 256;
            int br = c >> 4, bc = c & 15;
            *(uint4*)&Bs[br * 136 + bc * 8] =
                *(const uint4*)&Bp[(size_t)(k0 + br) * N + bn + bc * 8];
        }
        __syncthreads();
#pragma unroll
        for (int s = 0; s < 2; s++) {
            uint32_t a[2][4];
            const int lr = lane & 15, lc = lane >> 4;
#pragma unroll
            for (int t = 0; t < 2; t++)
                ldsm_x4(a[t], &As[(wm * 32 + t * 16 + lr) * 40 + s * 16 + lc * 8]);
            uint32_t b[8][2];
            const int brow = s * 16 + (lane & 7) + (lane & 8);
            const int bco  = (lane & 16) >> 1;
#pragma unroll
            for (int p = 0; p < 4; p++) {
                uint32_t r[4];
                ldsm_x4_t(r, &Bs[brow * 136 + wn * 64 + p * 16 + bco]);
                b[2*p][0] = r[0]; b[2*p][1] = r[1];
                b[2*p+1][0] = r[2]; b[2*p+1][1] = r[3];
            }
#pragma unroll
            for (int t = 0; t < 2; t++)
#pragma unroll
                for (int j = 0; j < 8; j++)
                    mma16816(acc[t][j], a[t], b[j]);
        }
        __syncthreads();
    }

    // epilogue
#pragma unroll
    for (int t = 0; t < 2; t++) {
        int r0 = bm + wm * 32 + t * 16 + (lane >> 2);
        float iz0 = Zr ? 1.0f / Zr[r0 - bm + bm] : 1.0f;        // Zr indexed by global row
        float iz1 = Zr ? 1.0f / Zr[r0 + 8] : 1.0f;
        if (Zr) iz0 = 1.0f / Zr[r0];
#pragma unroll
        for (int j = 0; j < 8; j++) {
            int col = bn + wn * 64 + j * 8 + (lane & 3) * 2;
            float c0 = acc[t][j][0] * iz0, c1 = acc[t][j][1] * iz0;
            float c2 = acc[t][j][2] * iz1, c3 = acc[t][j][3] * iz1;
            *(float2*)&Cf[(size_t)r0 * N + col]       = make_float2(c0, c1);
            *(float2*)&Cf[(size_t)(r0 + 8) * N + col] = make_float2(c2, c3);
            if (Cb) {
                __nv_bfloat162 b0; b0.x = __float2bfloat16(c0); b0.y = __float2bfloat16(c1);
                __nv_bfloat162 b1; b1.x = __float2bfloat16(c2); b1.y = __float2bfloat16(c3);
                *(__nv_bfloat162*)&Cb[(size_t)r0 * N + col]       = b0;
                *(__nv_bfloat162*)&Cb[(size_t)(r0 + 8) * N + col] = b1;
            }
        }
    }
}

// ---------------- e_src/e_dst dot products (one warp per (h,n)) -------------
__global__ __launch_bounds__(256) void k_edot(const float* __restrict__ a1) {
    const int w    = (blockIdx.x * blockDim.x + threadIdx.x) >> 5;
    const int lane = threadIdx.x & 31;
    const int h = w >> 12;
    const int n = w & (NN - 1);
    const float* hrow = g_h1f + ((size_t)h * NN + n) * FHID;
    const float* asrc = a1 + h * 2 * FHID;
    const float* adst = asrc + FHID;
    float s = 0.0f, d = 0.0f;
#pragma unroll
    for (int o = lane; o < FHID; o += 32) {
        float v = hrow[o];
        s += v * asrc[o];
        d += v * adst[o];
    }
#pragma unroll
    for (int off = 16; off; off >>= 1) {
        s += __shfl_xor_sync(0xffffffffu, s, off);
        d += __shfl_xor_sync(0xffffffffu, d, off);
    }
    if (lane == 0) { g_esrc1[h*NN + n] = s; g_edst1[h*NN + n] = d; }
}

// ---------------- exp decomposition prep ------------------------------------
// p(n,m) = exp(lrelu(es+ed) - rm(n)),  rm(n) = lrelu(es(n) + max_m ed)
//        = s>=0 ? A1[n]*B1[m] : A2[n]*B2[m]
__global__ __launch_bounds__(256) void k_prep(int layer) {
    const float *es, *ed; float *A1, *A2, *B1, *B2;
    int h = blockIdx.x;
    if (layer == 0) {
        es = g_esrc1 + h*NN; ed = g_edst1 + h*NN;
        A1 = g_A11 + h*NN; A2 = g_A21 + h*NN; B1 = g_B11 + h*NN; B2 = g_B21 + h*NN;
    } else {
        es = g_esrc2; ed = g_edst2;
        A1 = g_A12; A2 = g_A22; B1 = g_B12; B2 = g_B22;
    }
    __shared__ float red[8];
    const int tid = threadIdx.x, lane = tid & 31, wid = tid >> 5;
    float mx = -3.4e38f;
    for (int m = tid; m < NN; m += 256) mx = fmaxf(mx, ed[m]);
#pragma unroll
    for (int off = 16; off; off >>= 1) mx = fmaxf(mx, __shfl_xor_sync(0xffffffffu, mx, off));
    if (lane == 0) red[wid] = mx;
    __syncthreads();
    float maxed = red[0];
#pragma unroll
    for (int w = 1; w < 8; w++) maxed = fmaxf(maxed, red[w]);

    for (int i = tid; i < NN; i += 256) {
        float e = es[i];
        float se = e + maxed;
        float rm = se >= 0.0f ? se : 0.2f * se;
        A1[i] = __expf(e - rm);
        A2[i] = __expf(0.2f * e - rm);
        float d = ed[i];
        B1[i] = __expf(d);
        B2[i] = __expf(0.2f * d);
    }
}

// ---------------- P generation (layer 1), fused Z ---------------------------
// block = 16 rows x 1 head, m processed in 1024-tiles
__global__ __launch_bounds__(256) void k_pgen() {
    const int h  = blockIdx.y;
    const int n0 = blockIdx.x * 16;
    const float* ed = g_edst1 + h*NN;
    const float* B1 = g_B11 + h*NN;
    const float* B2 = g_B21 + h*NN;
    __shared__ float sed[1024], sb1[1024], sb2[1024];
    __shared__ unsigned sbits[16][32];
    __shared__ float sA1[16], sA2[16], ses[16], zsh[16];
    const int tid = threadIdx.x, lane = tid & 31;
    if (tid < 16) {
        sA1[tid] = g_A11[h*NN + n0 + tid];
        sA2[tid] = g_A21[h*NN + n0 + tid];
        ses[tid] = g_esrc1[h*NN + n0 + tid];
        zsh[tid] = 0.0f;
    }
    float z[16];
#pragma unroll
    for (int r = 0; r < 16; r++) z[r] = 0.0f;

    for (int mt = 0; mt < 4; mt++) {
        __syncthreads();
#pragma unroll
        for (int j = 0; j < 4; j++) {
            int m = tid + j * 256;
            sed[m] = ed[mt*1024 + m];
            sb1[m] = B1[mt*1024 + m];
            sb2[m] = B2[mt*1024 + m];
        }
#pragma unroll
        for (int j = 0; j < 2; j++) {
            int w = tid + j * 256;
            sbits[w >> 5][w & 31] = g_adjbits[(size_t)(n0 + (w >> 5)) * 128 + mt*32 + (w & 31)];
        }
        __syncthreads();
#pragma unroll
        for (int j = 0; j < 4; j++) {
            int m = tid + j * 256;
            float d = sed[m], b1 = sb1[m], b2 = sb2[m];
            unsigned sel = 1u << (m & 31);
            int wi = m >> 5;
            __nv_bfloat16* prow = g_P1 + (size_t)h*NN*NN + (size_t)n0*NN + mt*1024 + m;
#pragma unroll
            for (int r = 0; r < 16; r++) {
                float s = ses[r] + d;
                float p = (s >= 0.0f) ? sA1[r] * b1 : sA2[r] * b2;
                if (!(sbits[r][wi] & sel)) p = 0.0f;
                __nv_bfloat16 pb = __float2bfloat16(p);
                prow[(size_t)r * NN] = pb;
                z[r] += __bfloat162float(pb);
            }
        }
    }
#pragma unroll
    for (int r = 0; r < 16; r++) {
#pragma unroll
        for (int off = 16; off; off >>= 1)
            z[r] += __shfl_xor_sync(0xffffffffu, z[r], off);
        if (lane == 0) atomicAdd(&zsh[r], z[r]);
    }
    __syncthreads();
    if (tid < 16) g_Z1[h*NN + n0 + tid] = zsh[tid];
}

// ---------------- mean over heads + relu ------------------------------------
__global__ __launch_bounds__(256) void k4_meanrelu() {
    const int i = blockIdx.x * 256 + threadIdx.x;
    const int S = NN * FHID;
    float v = 0.25f * (g_out1[i] + g_out1[i + S] + g_out1[i + 2*S] + g_out1[i + 3*S]);
    g_hmid[i] = v > 0.0f ? v : 0.0f;
}

// ---------------- layer 2 feature GEMM + e2 dots ----------------------------
__global__ __launch_bounds__(256) void k5_layer2(const float* __restrict__ W2,
                                                 const float* __restrict__ a2) {
    __shared__ float sW[FHID * FCLS];
    const int tid = threadIdx.x;
    for (int i = tid; i < FHID * FCLS; i += 256) sW[i] = W2[i];
    __syncthreads();
    const int r = tid >> 4;
    const int o = tid & 15;
    const int n = blockIdx.x * 16 + r;
    const float* hr = g_hmid + (size_t)n * FHID;
    float v = 0.0f;
#pragma unroll 8
    for (int f = 0; f < FHID; f++) v += hr[f] * sW[f * FCLS + o];
    g_h2[n * FCLS + o] = v;
    float vs = v * a2[o];
    float vd = v * a2[FCLS + o];
#pragma unroll
    for (int off = 8; off; off >>= 1) {
        vs += __shfl_xor_sync(0xffffffffu, vs, off);
        vd += __shfl_xor_sync(0xffffffffu, vd, off);
    }
    if (o == 0) { g_esrc2[n] = vs; g_edst2[n] = vd; }
}

// ---------------- layer 2 fused attention + log_softmax ---------------------
// block = 16 rows; 16 lane-groups x 16 lanes; single pass (bound-based rm)
__global__ __launch_bounds__(256) void k7_fused(float* __restrict__ out) {
    const int n0 = blockIdx.x * 16;
    __shared__ float sh2[512 * 17];
    __shared__ float sed[512], sb1[512], sb2[512];
    __shared__ unsigned sbits[16][16];
    __shared__ float ses[16], sA1[16], sA2[16];
    const int tid = threadIdx.x;
    const int g = tid >> 4, l = tid & 15;
    if (tid < 16) {
        ses[tid] = g_esrc2[n0 + tid];
        sA1[tid] = g_A12[n0 + tid];
        sA2[tid] = g_A22[n0 + tid];
    }
    float acc[16];
#pragma unroll
    for (int o = 0; o < 16; o++) acc[o] = 0.0f;
    float z = 0.0f;

    for (int mt = 0; mt < 8; mt++) {
        __syncthreads();
#pragma unroll
        for (int j = 0; j < 32; j++) {
            int idx = tid + j * 256;
            int m = idx >> 4, o = idx & 15;
            sh2[m * 17 + o] = g_h2[(size_t)(mt*512 + m) * 16 + o];
        }
#pragma unroll
        for (int j = 0; j < 2; j++) {
            int m = tid + j * 256;
            sed[m] = g_edst2[mt*512 + m];
            sb1[m] = g_B12[mt*512 + m];
            sb2[m] = g_B22[mt*512 + m];
        }
        {
            int w = tid;
            if (w < 256) sbits[w >> 4][w & 15] =
                g_adjbits[(size_t)(n0 + (w >> 4)) * 128 + mt*16 + (w & 15)];
        }
        __syncthreads();
        float eg = ses[g], a1 = sA1[g], a2 = sA2[g];
#pragma unroll 4
        for (int k = 0; k < 32; k++) {
            int m = l + k * 16;
            float d = sed[m];
            float s = eg + d;
            float p = (s >= 0.0f) ? a1 * sb1[m] : a2 * sb2[m];
            if (!((sbits[g][m >> 5] >> (m & 31)) & 1)) p = 0.0f;
            z += p;
            const float* hp = &sh2[m * 17];
#pragma unroll
            for (int o = 0; o < 16; o++) acc[o] += p * hp[o];
        }
    }
    // reduce across the 16 lanes of each group
#pragma unroll
    for (int off = 8; off; off >>= 1) {
        z += __shfl_xor_sync(0xffffffffu, z, off);
#pragma unroll
        for (int o = 0; o < 16; o++)
            acc[o] += __shfl_xor_sync(0xffffffffu, acc[o], off);
    }
    if (l == 0) {
        float inv = 1.0f / z;
        float t[16], mx = -3.4e38f;
#pragma unroll
        for (int o = 0; o < 16; o++) { t[o] = acc[o] * inv; mx = fmaxf(mx, t[o]); }
        float se = 0.0f;
#pragma unroll
        for (int o = 0; o < 16; o++) se += __expf(t[o] - mx);
        float lg = mx + __logf(se);
#pragma unroll
        for (int o = 0; o < 16; o++)
            out[(size_t)(n0 + g) * 16 + o] = t[o] - lg;
    }
}

// ---------------------------------------------------------------------------
extern "C" void kernel_launch(void* const* d_in, const int* in_sizes, int n_in,
                              void* d_out, int out_size) {
    const float* x   = (const float*)d_in[0];
    const int*   adj = (const int*)  d_in[1];
    const float* W1  = (const float*)d_in[2];
    const float* a1  = (const float*)d_in[3];
    const float* W2  = (const float*)d_in[4];
    const float* a2  = (const float*)d_in[5];
    float* out = (float*)d_out;

    // conversions + adjacency pack
    {
        __nv_bfloat16* xb; cudaGetSymbolAddress((void**)&xb, g_xb);
        __nv_bfloat16* w1b; cudaGetSymbolAddress((void**)&w1b, g_W1b);
        k_cvt<<<(NN*FIN + 255)/256, 256>>>(x, xb, NN*FIN);
        k_cvt<<<(NHD*FIN*FHID + 255)/256, 256>>>(W1, w1b, NHD*FIN*FHID);
    }
    k_pack<<<(NN*NN/32)/8, 256>>>(adj);

    // layer 1
    dim3 gg(NN/128, FHID/128, NHD);
    k_gemm_mma<<<gg, 256>>>(0);                     // h1 = x @ W1[h]
    k_edot<<<(NHD*NN)/8, 256>>>(a1);
    k_prep<<<NHD, 256>>>(0);
    dim3 gp(NN/16, NHD);
    k_pgen<<<gp, 256>>>();                          // P1 (bf16) + Z1
    k_gemm_mma<<<gg, 256>>>(1);                     // out1 = (P1 @ h1b) / Z

    // layer 2
    k4_meanrelu<<<(NN*FHID)/256, 256>>>();
    k5_layer2<<<NN/16, 256>>>(W2, a2);
    k_prep<<<1, 256>>>(1);
    k7_fused<<<NN/16, 256>>>(out);
}

// round 3
// speedup vs baseline: 5.2043x; 1.0393x over previous
#include <cuda_runtime.h>
#include <cuda_bf16.h>
#include <cstdint>

#define NN    4096
#define FIN   512
#define FHID  256
#define FCLS  16
#define NHD   4

// ---------------- scratch (static device globals) ---------------------------
__device__ float         g_h1f [NHD*NN*FHID];         // 16 MB (for e-dot products)
__device__ __nv_bfloat16 g_h1b [NHD*NN*FHID];         // 8 MB  (GEMM B operand)
__device__ float         g_out1[NHD*NN*FHID];         // 16 MB (normalized attention out)
__device__ float         g_hmid[NN*FHID];             // 4 MB
__device__ __nv_bfloat16 g_xb  [NN*FIN];              // 4 MB
__device__ __nv_bfloat16 g_W1b [NHD*FIN*FHID];        // 1 MB
__device__ unsigned      g_adjbits[(size_t)NN*NN/32]; // 2 MB
__device__ float4        g_cp1[NHD*NN];               // (ed, B1, B2, 0) per (h,m)
__device__ float g_esrc1[NHD*NN], g_edst1[NHD*NN];
__device__ float g_A11[NHD*NN], g_A21[NHD*NN];
__device__ float g_h2[NN*FCLS];
__device__ float g_esrc2[NN], g_edst2[NN];
__device__ float g_A12[NN], g_A22[NN], g_B12[NN], g_B22[NN];

// ---------------- PTX helpers ------------------------------------------------
__device__ __forceinline__ void mma16816(float* c, const uint32_t* a, const uint32_t* b) {
    asm volatile("mma.sync.aligned.m16n8k16.row.col.f32.bf16.bf16.f32 "
                 "{%0,%1,%2,%3}, {%4,%5,%6,%7}, {%8,%9}, {%0,%1,%2,%3};\n"
                 : "+f"(c[0]), "+f"(c[1]), "+f"(c[2]), "+f"(c[3])
                 : "r"(a[0]), "r"(a[1]), "r"(a[2]), "r"(a[3]),
                   "r"(b[0]), "r"(b[1]));
}
__device__ __forceinline__ void ldsm_x4(uint32_t* r, const void* p) {
    uint32_t a = (uint32_t)__cvta_generic_to_shared(p);
    asm volatile("ldmatrix.sync.aligned.m8n8.x4.shared.b16 {%0,%1,%2,%3}, [%4];"
                 : "=r"(r[0]), "=r"(r[1]), "=r"(r[2]), "=r"(r[3]) : "r"(a));
}
__device__ __forceinline__ void ldsm_x4_t(uint32_t* r, const void* p) {
    uint32_t a = (uint32_t)__cvta_generic_to_shared(p);
    asm volatile("ldmatrix.sync.aligned.m8n8.x4.trans.shared.b16 {%0,%1,%2,%3}, [%4];"
                 : "=r"(r[0]), "=r"(r[1]), "=r"(r[2]), "=r"(r[3]) : "r"(a));
}
__device__ __forceinline__ void cpa16(void* s, const void* g) {
    uint32_t sa = (uint32_t)__cvta_generic_to_shared(s);
    asm volatile("cp.async.cg.shared.global [%0], [%1], 16;\n" :: "r"(sa), "l"(g));
}
#define CP_COMMIT asm volatile("cp.async.commit_group;\n" ::: "memory")
#define CP_WAIT0  asm volatile("cp.async.wait_group 0;\n" ::: "memory")

// shared mma micro-kernel: 128x128 block tile, 4x2 warp grid, warp tile 32x64
__device__ __forceinline__ void mma_step(const __nv_bfloat16* As, const __nv_bfloat16* Bs,
                                         int wm, int wn, int lane, float acc[2][8][4]) {
#pragma unroll
    for (int s = 0; s < 2; s++) {
        uint32_t a[2][4];
        const int lr = lane & 15, lc = lane >> 4;
#pragma unroll
        for (int t = 0; t < 2; t++)
            ldsm_x4(a[t], &As[(wm * 32 + t * 16 + lr) * 40 + s * 16 + lc * 8]);
        uint32_t b[8][2];
        const int brow = s * 16 + (lane & 7) + (lane & 8);
        const int bco  = (lane & 16) >> 1;
#pragma unroll
        for (int p = 0; p < 4; p++) {
            uint32_t r[4];
            ldsm_x4_t(r, &Bs[brow * 136 + wn * 64 + p * 16 + bco]);
            b[2*p][0] = r[0]; b[2*p][1] = r[1];
            b[2*p+1][0] = r[2]; b[2*p+1][1] = r[3];
        }
#pragma unroll
        for (int t = 0; t < 2; t++)
#pragma unroll
            for (int j = 0; j < 8; j++)
                mma16816(acc[t][j], a[t], b[j]);
    }
}

// ---------------- conversions ------------------------------------------------
__global__ void k_cvt(const float* __restrict__ src, __nv_bfloat16* __restrict__ dst, int n) {
    int i = blockIdx.x * 256 + threadIdx.x;
    if (i < n) dst[i] = __float2bfloat16(src[i]);
}

// ---------------- adjacency bit-pack ----------------------------------------
__global__ void k_pack(const int* __restrict__ adj) {
    int w = blockIdx.x * 8 + (threadIdx.x >> 5);
    int lane = threadIdx.x & 31;
    int v = adj[(size_t)w * 32 + lane];
    unsigned m = __ballot_sync(0xffffffffu, v != 0);
    if (lane == 0) g_adjbits[w] = m;
}

// ---------------- K1: h1 = xb @ W1b[h], double-buffered cp.async ------------
__global__ __launch_bounds__(256, 2) void k1_mma() {
    const int h  = blockIdx.z;
    const int bm = blockIdx.x * 128;
    const int bn = blockIdx.y * 128;
    const __nv_bfloat16* A  = g_xb;
    const __nv_bfloat16* Bp = g_W1b + (size_t)h * FIN * FHID;

    __shared__ __nv_bfloat16 As[2][128 * 40];
    __shared__ __nv_bfloat16 Bs[2][32 * 136];

    const int tid = threadIdx.x;
    const int warp = tid >> 5, lane = tid & 31;
    const int wm = warp & 3, wn = warp >> 2;

    float acc[2][8][4];
#pragma unroll
    for (int t = 0; t < 2; t++)
#pragma unroll
        for (int j = 0; j < 8; j++)
#pragma unroll
            for (int i = 0; i < 4; i++) acc[t][j][i] = 0.0f;

    auto loadA = [&](int buf, int k0) {
#pragma unroll
        for (int c0 = 0; c0 < 2; c0++) {
            int c = tid + c0 * 256;
            int row = c >> 2, cc = c & 3;
            cpa16(&As[buf][row * 40 + cc * 8],
                  &A[(size_t)(bm + row) * FIN + k0 + cc * 8]);
        }
    };
    auto loadB = [&](int buf, int k0) {
#pragma unroll
        for (int c0 = 0; c0 < 2; c0++) {
            int c = tid + c0 * 256;
            int br = c >> 4, bc = c & 15;
            cpa16(&Bs[buf][br * 136 + bc * 8],
                  &Bp[(size_t)(k0 + br) * FHID + bn + bc * 8]);
        }
    };

    loadA(0, 0); loadB(0, 0);
    CP_COMMIT; CP_WAIT0; __syncthreads();

    const int S = FIN / 32;   // 16
    for (int k = 0; k < S; k++) {
        int cur = k & 1, nxt = cur ^ 1;
        if (k + 1 < S) {
            loadA(nxt, (k + 1) * 32);
            loadB(nxt, (k + 1) * 32);
            CP_COMMIT;
        }
        mma_step(As[cur], Bs[cur], wm, wn, lane, acc);
        CP_WAIT0; __syncthreads();
    }

    float*         Cf = g_h1f + (size_t)h * NN * FHID;
    __nv_bfloat16* Cb = g_h1b + (size_t)h * NN * FHID;
#pragma unroll
    for (int t = 0; t < 2; t++) {
        int r0 = bm + wm * 32 + t * 16 + (lane >> 2);
#pragma unroll
        for (int j = 0; j < 8; j++) {
            int col = bn + wn * 64 + j * 8 + (lane & 3) * 2;
            float c0 = acc[t][j][0], c1 = acc[t][j][1];
            float c2 = acc[t][j][2], c3 = acc[t][j][3];
            *(float2*)&Cf[(size_t)r0 * FHID + col]       = make_float2(c0, c1);
            *(float2*)&Cf[(size_t)(r0 + 8) * FHID + col] = make_float2(c2, c3);
            __nv_bfloat162 b0; b0.x = __float2bfloat16(c0); b0.y = __float2bfloat16(c1);
            __nv_bfloat162 b1; b1.x = __float2bfloat16(c2); b1.y = __float2bfloat16(c3);
            *(__nv_bfloat162*)&Cb[(size_t)r0 * FHID + col]       = b0;
            *(__nv_bfloat162*)&Cb[(size_t)(r0 + 8) * FHID + col] = b1;
        }
    }
}

// ---------------- e_src/e_dst dot products ----------------------------------
__global__ __launch_bounds__(256) void k_edot(const float* __restrict__ a1) {
    const int w    = (blockIdx.x * blockDim.x + threadIdx.x) >> 5;
    const int lane = threadIdx.x & 31;
    const int h = w >> 12;
    const int n = w & (NN - 1);
    const float* hrow = g_h1f + ((size_t)h * NN + n) * FHID;
    const float* asrc = a1 + h * 2 * FHID;
    const float* adst = asrc + FHID;
    float s = 0.0f, d = 0.0f;
#pragma unroll
    for (int o = lane; o < FHID; o += 32) {
        float v = hrow[o];
        s += v * asrc[o];
        d += v * adst[o];
    }
#pragma unroll
    for (int off = 16; off; off >>= 1) {
        s += __shfl_xor_sync(0xffffffffu, s, off);
        d += __shfl_xor_sync(0xffffffffu, d, off);
    }
    if (lane == 0) { g_esrc1[h*NN + n] = s; g_edst1[h*NN + n] = d; }
}

// ---------------- exp decomposition prep ------------------------------------
// p(n,m) = exp(lrelu(es+ed) - rm(n)) = s>=0 ? A1[n]*B1[m] : A2[n]*B2[m]
// rm(n) = lrelu(es(n) + max_m ed) >= row max (softmax shift-invariant, safe)
__global__ __launch_bounds__(256) void k_prep(int layer) {
    const float *es, *ed;
    int h = blockIdx.x;
    if (layer == 0) { es = g_esrc1 + h*NN; ed = g_edst1 + h*NN; }
    else            { es = g_esrc2;        ed = g_edst2; }
    __shared__ float red[8];
    const int tid = threadIdx.x, lane = tid & 31, wid = tid >> 5;
    float mx = -3.4e38f;
    for (int m = tid; m < NN; m += 256) mx = fmaxf(mx, ed[m]);
#pragma unroll
    for (int off = 16; off; off >>= 1) mx = fmaxf(mx, __shfl_xor_sync(0xffffffffu, mx, off));
    if (lane == 0) red[wid] = mx;
    __syncthreads();
    float maxed = red[0];
#pragma unroll
    for (int w = 1; w < 8; w++) maxed = fmaxf(maxed, red[w]);

    for (int i = tid; i < NN; i += 256) {
        float e = es[i];
        float se = e + maxed;
        float rm = se >= 0.0f ? se : 0.2f * se;
        float a1 = __expf(e - rm);
        float a2 = __expf(0.2f * e - rm);
        float d = ed[i];
        float b1 = __expf(d);
        float b2 = __expf(0.2f * d);
        if (layer == 0) {
            g_A11[h*NN + i] = a1; g_A21[h*NN + i] = a2;
            g_cp1[h*NN + i] = make_float4(d, b1, b2, 0.0f);
        } else {
            g_A12[i] = a1; g_A22[i] = a2;
            g_B12[i] = b1; g_B22[i] = b2;
        }
    }
}

// ---------------- fused attention GEMM (flash-style, no P materialization) --
// out1[h] = softmax(e)[128-row tile] @ h1b[h] ; A-tile generated in smem per
// k-step; Z accumulated in-register across full K, applied in epilogue.
__device__ __forceinline__ float gen_tile(__nv_bfloat16* Asb, const float4* scol,
                                          unsigned abw, int row, int half,
                                          float es, float a1v, float a2v) {
    float zacc = 0.0f;
#pragma unroll
    for (int c0 = 0; c0 < 2; c0++) {
        float p[8];
#pragma unroll
        for (int j = 0; j < 8; j++) {
            int col = half * 16 + c0 * 8 + j;
            float4 cv = scol[col];
            float s = es + cv.x;
            float v = (s >= 0.0f) ? a1v * cv.y : a2v * cv.z;
            v = ((abw >> col) & 1u) ? v : 0.0f;
            p[j] = v; zacc += v;
        }
        __nv_bfloat162 q[4];
#pragma unroll
        for (int j = 0; j < 4; j++) q[j] = __floats2bfloat162_rn(p[2*j], p[2*j+1]);
        *(uint4*)&Asb[row * 40 + half * 16 + c0 * 8] = *(uint4*)q;
    }
    return zacc;
}

__global__ __launch_bounds__(256, 2) void k_attn_fused() {
    const int h  = blockIdx.z;
    const int bm = blockIdx.x * 128;
    const int bn = blockIdx.y * 128;

    __shared__ __nv_bfloat16 As[2][128 * 40];
    __shared__ __nv_bfloat16 Bs[2][32 * 136];
    __shared__ float4 scol[2][32];
    __shared__ float  s_zp[256];
    __shared__ float  s_zi[128];

    const int tid  = threadIdx.x;
    const int warp = tid >> 5, lane = tid & 31;
    const int wm = warp & 3, wn = warp >> 2;
    const int row = tid >> 1, half = tid & 1;

    const float es  = g_esrc1[h*NN + bm + row];
    const float a1v = g_A11 [h*NN + bm + row];
    const float a2v = g_A21 [h*NN + bm + row];
    const float4*   cp = g_cp1 + (size_t)h * NN;           // indexed by m
    const unsigned* ab = g_adjbits + (size_t)(bm + row) * (NN/32);
    const __nv_bfloat16* Bp = g_h1b + (size_t)h * NN * FHID;

    float acc[2][8][4];
#pragma unroll
    for (int t = 0; t < 2; t++)
#pragma unroll
        for (int j = 0; j < 8; j++)
#pragma unroll
            for (int i = 0; i < 4; i++) acc[t][j][i] = 0.0f;
    float zacc = 0.0f;

    auto loadB = [&](int buf, int k0) {
#pragma unroll
        for (int c0 = 0; c0 < 2; c0++) {
            int c = tid + c0 * 256;
            int br = c >> 4, bc = c & 15;
            cpa16(&Bs[buf][br * 136 + bc * 8],
                  &Bp[(size_t)(k0 + br) * FHID + bn + bc * 8]);
        }
    };

    const int S = NN / 32;   // 128

    // ---- prologue: scol[0] <- step0; gen As[0]; Bs[0]; scol[1] <- step1 ----
    if (tid < 32) cpa16(&scol[0][tid], cp + tid);
    CP_COMMIT; CP_WAIT0; __syncthreads();
    unsigned abw = ab[0];
    unsigned abn = ab[1];
    zacc += gen_tile(As[0], scol[0], abw, row, half, es, a1v, a2v);
    abw = abn;
    loadB(0, 0);
    if (tid < 32) cpa16(&scol[1][tid], cp + 32 + tid);
    CP_COMMIT; CP_WAIT0; __syncthreads();

    // ---- main pipeline ----
    for (int k = 0; k < S; k++) {
        int cur = k & 1, nxt = cur ^ 1;
        if (k + 1 < S) {
            loadB(nxt, (k + 1) * 32);
            if (tid < 32 && k + 2 < S) cpa16(&scol[cur][tid], cp + (k + 2) * 32 + tid);
            CP_COMMIT;
            unsigned abn2 = (k + 2 < S) ? ab[k + 2] : 0u;
            zacc += gen_tile(As[nxt], scol[nxt], abw, row, half, es, a1v, a2v);
            abw = abn2;
        }
        mma_step(As[cur], Bs[cur], wm, wn, lane, acc);
        CP_WAIT0; __syncthreads();
    }

    // ---- Z reduction (2 threads per row) ----
    s_zp[tid] = zacc;
    __syncthreads();
    if (tid < 128) s_zi[tid] = 1.0f / (s_zp[2*tid] + s_zp[2*tid + 1]);
    __syncthreads();

    // ---- epilogue: normalized fp32 out1 ----
    float* Cf = g_out1 + (size_t)h * NN * FHID;
#pragma unroll
    for (int t = 0; t < 2; t++) {
        int lr0 = wm * 32 + t * 16 + (lane >> 2);
        float iz0 = s_zi[lr0], iz1 = s_zi[lr0 + 8];
        int r0 = bm + lr0;
#pragma unroll
        for (int j = 0; j < 8; j++) {
            int col = bn + wn * 64 + j * 8 + (lane & 3) * 2;
            *(float2*)&Cf[(size_t)r0 * FHID + col] =
                make_float2(acc[t][j][0] * iz0, acc[t][j][1] * iz0);
            *(float2*)&Cf[(size_t)(r0 + 8) * FHID + col] =
                make_float2(acc[t][j][2] * iz1, acc[t][j][3] * iz1);
        }
    }
}

// ---------------- mean over heads + relu ------------------------------------
__global__ __launch_bounds__(256) void k4_meanrelu() {
    const int i = blockIdx.x * 256 + threadIdx.x;
    const int S = NN * FHID;
    float v = 0.25f * (g_out1[i] + g_out1[i + S] + g_out1[i + 2*S] + g_out1[i + 3*S]);
    g_hmid[i] = v > 0.0f ? v : 0.0f;
}

// ---------------- layer 2 feature GEMM + e2 dots ----------------------------
__global__ __launch_bounds__(256) void k5_layer2(const float* __restrict__ W2,
                                                 const float* __restrict__ a2) {
    __shared__ float sW[FHID * FCLS];
    const int tid = threadIdx.x;
    for (int i = tid; i < FHID * FCLS; i += 256) sW[i] = W2[i];
    __syncthreads();
    const int r = tid >> 4;
    const int o = tid & 15;
    const int n = blockIdx.x * 16 + r;
    const float* hr = g_hmid + (size_t)n * FHID;
    float v = 0.0f;
#pragma unroll 8
    for (int f = 0; f < FHID; f++) v += hr[f] * sW[f * FCLS + o];
    g_h2[n * FCLS + o] = v;
    float vs = v * a2[o];
    float vd = v * a2[FCLS + o];
#pragma unroll
    for (int off = 8; off; off >>= 1) {
        vs += __shfl_xor_sync(0xffffffffu, vs, off);
        vd += __shfl_xor_sync(0xffffffffu, vd, off);
    }
    if (o == 0) { g_esrc2[n] = vs; g_edst2[n] = vd; }
}

// ---------------- layer 2 fused attention + log_softmax ---------------------
__global__ __launch_bounds__(256) void k7_fused(float* __restrict__ out) {
    const int n0 = blockIdx.x * 16;
    __shared__ float sh2[512 * 17];
    __shared__ float sed[512], sb1[512], sb2[512];
    __shared__ unsigned sbits[16][16];
    __shared__ float ses[16], sA1[16], sA2[16];
    const int tid = threadIdx.x;
    const int g = tid >> 4, l = tid & 15;
    if (tid < 16) {
        ses[tid] = g_esrc2[n0 + tid];
        sA1[tid] = g_A12[n0 + tid];
        sA2[tid] = g_A22[n0 + tid];
    }
    float acc[16];
#pragma unroll
    for (int o = 0; o < 16; o++) acc[o] = 0.0f;
    float z = 0.0f;

    for (int mt = 0; mt < 8; mt++) {
        __syncthreads();
#pragma unroll
        for (int j = 0; j < 32; j++) {
            int idx = tid + j * 256;
            int m = idx >> 4, o = idx & 15;
            sh2[m * 17 + o] = g_h2[(size_t)(mt*512 + m) * 16 + o];
        }
#pragma unroll
        for (int j = 0; j < 2; j++) {
            int m = tid + j * 256;
            sed[m] = g_edst2[mt*512 + m];
            sb1[m] = g_B12[mt*512 + m];
            sb2[m] = g_B22[mt*512 + m];
        }
        {
            int w = tid;
            if (w < 256) sbits[w >> 4][w & 15] =
                g_adjbits[(size_t)(n0 + (w >> 4)) * 128 + mt*16 + (w & 15)];
        }
        __syncthreads();
        float eg = ses[g], a1 = sA1[g], a2 = sA2[g];
#pragma unroll 4
        for (int k = 0; k < 32; k++) {
            int m = l + k * 16;
            float d = sed[m];
            float s = eg + d;
            float p = (s >= 0.0f) ? a1 * sb1[m] : a2 * sb2[m];
            if (!((sbits[g][m >> 5] >> (m & 31)) & 1)) p = 0.0f;
            z += p;
            const float* hp = &sh2[m * 17];
#pragma unroll
            for (int o = 0; o < 16; o++) acc[o] += p * hp[o];
        }
    }
#pragma unroll
    for (int off = 8; off; off >>= 1) {
        z += __shfl_xor_sync(0xffffffffu, z, off);
#pragma unroll
        for (int o = 0; o < 16; o++)
            acc[o] += __shfl_xor_sync(0xffffffffu, acc[o], off);
    }
    if (l == 0) {
        float inv = 1.0f / z;
        float t[16], mx = -3.4e38f;
#pragma unroll
        for (int o = 0; o < 16; o++) { t[o] = acc[o] * inv; mx = fmaxf(mx, t[o]); }
        float se = 0.0f;
#pragma unroll
        for (int o = 0; o < 16; o++) se += __expf(t[o] - mx);
        float lg = mx + __logf(se);
#pragma unroll
        for (int o = 0; o < 16; o++)
            out[(size_t)(n0 + g) * 16 + o] = t[o] - lg;
    }
}

// ---------------------------------------------------------------------------
extern "C" void kernel_launch(void* const* d_in, const int* in_sizes, int n_in,
                              void* d_out, int out_size) {
    const float* x   = (const float*)d_in[0];
    const int*   adj = (const int*)  d_in[1];
    const float* W1  = (const float*)d_in[2];
    const float* a1  = (const float*)d_in[3];
    const float* W2  = (const float*)d_in[4];
    const float* a2  = (const float*)d_in[5];
    float* out = (float*)d_out;

    __nv_bfloat16* xb;  cudaGetSymbolAddress((void**)&xb,  g_xb);
    __nv_bfloat16* w1b; cudaGetSymbolAddress((void**)&w1b, g_W1b);
    k_cvt<<<(NN*FIN + 255)/256, 256>>>(x, xb, NN*FIN);
    k_cvt<<<(NHD*FIN*FHID + 255)/256, 256>>>(W1, w1b, NHD*FIN*FHID);
    k_pack<<<(NN*NN/32)/8, 256>>>(adj);

    // layer 1
    dim3 gg(NN/128, FHID/128, NHD);
    k1_mma<<<gg, 256>>>();                 // h1 = x @ W1[h]
    k_edot<<<(NHD*NN)/8, 256>>>(a1);
    k_prep<<<NHD, 256>>>(0);
    k_attn_fused<<<gg, 256>>>();           // out1 = softmax(e) @ h1b, fused P+Z

    // layer 2
    k4_meanrelu<<<(NN*FHID)/256, 256>>>();
    k5_layer2<<<NN/16, 256>>>(W2, a2);
    k_prep<<<1, 256>>>(1);
    k7_fused<<<NN/16, 256>>>(out);
}